// round 9
// baseline (speedup 1.0000x reference)
#include <cuda_runtime.h>
#include <math.h>

// DenseNetPWLNN fused kernel.
// Inputs (metadata order): x(524288x32), W0(5x32), W1(5x37), W2(5x42), W3(5x47),
// W4(5x52), Wout(2x57), bout(2), ctrs(250x2), wts(250x2x2), offsets(250x2).
// Output: (524288 x 2) float32.

#define BLOCK 256
#define N_FCNS 250

// padded dense-weight layout in shared memory (rows padded to mult of 4 floats):
// L0: fan 32 pad 32 off    0  (5*32 = 160)
// L1: fan 37 pad 40 off  160  (5*40 = 200)
// L2: fan 42 pad 44 off  360  (5*44 = 220)
// L3: fan 47 pad 48 off  580  (5*48 = 240)
// L4: fan 52 pad 52 off  820  (5*52 = 260)
// Wout: 2 x 60 off 1080 (fan 57)
#define SW_TOT 1200

// Correctly-rounded f32 tanh: promote to double, libdevice double tanh, round
// once. Best-performing tanh variant so far (R6 evidence: beats tanhf and the
// XLA rational) — reference tanh is CR-class.
__device__ __forceinline__ float tanh_cr(float x) {
    return (float)tanh((double)x);
}

template <int FANv, int FANPv, int OFFv>
__device__ __forceinline__ void dense_layer(const float* __restrict__ sW, float h[60]) {
    float acc[5];
#pragma unroll
    for (int j = 0; j < 5; ++j) {
        // gemm accumulation: acc = 0; ascending-k sequential fma (Eigen gebp /
        // cublas SIMT order). Zero padding at row end is exact.
        float a = 0.f;
#pragma unroll
        for (int i = 0; i < FANPv; i += 4) {
            float4 w = *reinterpret_cast<const float4*>(&sW[OFFv + j * FANPv + i]);
            a = fmaf(w.x, h[i + 0], a);
            a = fmaf(w.y, h[i + 1], a);
            a = fmaf(w.z, h[i + 2], a);
            a = fmaf(w.w, h[i + 3], a);
        }
        acc[j] = a;
    }
#pragma unroll
    for (int j = 0; j < 5; ++j) h[FANv + j] = tanh_cr(acc[j]);
}

__global__ void __launch_bounds__(BLOCK, 2)
densenet_pwlnn_kernel(const float* __restrict__ x,
                      const float* __restrict__ gW0, const float* __restrict__ gW1,
                      const float* __restrict__ gW2, const float* __restrict__ gW3,
                      const float* __restrict__ gW4,
                      const float* __restrict__ gWout, const float* __restrict__ gbout,
                      const float* __restrict__ gctrs, const float* __restrict__ gwts,
                      const float* __restrict__ goffs,
                      float* __restrict__ out, int n)
{
    __shared__ float sW[SW_TOT];
    __shared__ float sb[2];
    __shared__ float4 sC[N_FCNS];    // (cx, cy, |c|^2, 0); |c|^2 = add(mul,mul)
    __shared__ float4 sP4[N_FCNS];   // (w00, w01, w10, w11)
    __shared__ float2 sP2[N_FCNS];   // offsets - wts^T * ctrs

    const int tid = threadIdx.x;

    // ---------------- per-block preprocessing (tiny; weights hot in L2) ----------
    {
        const float* gw[5] = {gW0, gW1, gW2, gW3, gW4};
        const int fan[5]  = {32, 37, 42, 47, 52};
        const int fanp[5] = {32, 40, 44, 48, 52};
        const int off[5]  = {0, 160, 360, 580, 820};
#pragma unroll
        for (int l = 0; l < 5; ++l) {
            int nel = 5 * fanp[l];
            for (int e = tid; e < nel; e += BLOCK) {
                int r = e / fanp[l];
                int c = e - r * fanp[l];
                sW[off[l] + e] = (c < fan[l]) ? gw[l][r * fan[l] + c] : 0.f;
            }
        }
        for (int e = tid; e < 120; e += BLOCK) {
            int r = e / 60, c = e - r * 60;
            sW[1080 + e] = (c < 57) ? gWout[r * 57 + c] : 0.f;
        }
        if (tid < 2) sb[tid] = gbout[tid];
        for (int i = tid; i < N_FCNS; i += BLOCK) {
            float cx = gctrs[2 * i], cy = gctrs[2 * i + 1];
            // XLA reduce-of-products: add(mul(cx,cx), mul(cy,cy)) — NOT fma.
            float c2 = __fadd_rn(__fmul_rn(cx, cx), __fmul_rn(cy, cy));
            sC[i] = make_float4(cx, cy, c2, 0.f);
            float w00 = gwts[4 * i + 0], w01 = gwts[4 * i + 1];
            float w10 = gwts[4 * i + 2], w11 = gwts[4 * i + 3];
            sP4[i] = make_float4(w00, w01, w10, w11);
            float c0 = goffs[2 * i + 0] - (w00 * cx + w10 * cy);
            float c1 = goffs[2 * i + 1] - (w01 * cx + w11 * cy);
            sP2[i] = make_float2(c0, c1);
        }
    }
    __syncthreads();

    const int s = blockIdx.x * BLOCK + tid;
    if (s >= n) return;

    // ---------------- load x row, init padded h ----------------
    float h[60];
    {
        const float4* xr = reinterpret_cast<const float4*>(x + (size_t)s * 32);
#pragma unroll
        for (int k = 0; k < 8; ++k) {
            float4 v = xr[k];
            h[4 * k + 0] = v.x; h[4 * k + 1] = v.y;
            h[4 * k + 2] = v.z; h[4 * k + 3] = v.w;
        }
#pragma unroll
        for (int i = 32; i < 60; ++i) h[i] = 0.f;
    }

    // ---------------- dense tanh net (fully unrolled, LDS.128 broadcast) ---------
    dense_layer<32, 32,   0>(sW, h);
    dense_layer<37, 40, 160>(sW, h);
    dense_layer<42, 44, 360>(sW, h);
    dense_layer<47, 48, 580>(sW, h);
    dense_layer<52, 52, 820>(sW, h);

    // ---------------- enc = h @ Wout^T + bout (bias added AFTER dot, like ref) ---
    float e0, e1;
    {
        float a0 = 0.f, a1 = 0.f;
#pragma unroll
        for (int i = 0; i < 60; i += 4) {
            float4 w0 = *reinterpret_cast<const float4*>(&sW[1080 + i]);
            float4 w1 = *reinterpret_cast<const float4*>(&sW[1140 + i]);
            a0 = fmaf(w0.x, h[i + 0], a0); a1 = fmaf(w1.x, h[i + 0], a1);
            a0 = fmaf(w0.y, h[i + 1], a0); a1 = fmaf(w1.y, h[i + 1], a1);
            a0 = fmaf(w0.z, h[i + 2], a0); a1 = fmaf(w1.z, h[i + 2], a1);
            a0 = fmaf(w0.w, h[i + 3], a0); a1 = fmaf(w1.w, h[i + 3], a1);
        }
        e0 = __fadd_rn(a0, sb[0]);
        e1 = __fadd_rn(a1, sb[1]);
    }

    // ---------------- top-5 smallest d2 ----------------
    //   ee  = add(mul(e0,e0), mul(e1,e1))            (reduce of products)
    //   g   = add(mul(e0,cx), mul(e1,cy))            (FORM B: non-contracted
    //                                                 loop-fusion lowering)
    //   d2  = add(sub(ee, mul(2,g)), cc)             (elementwise fusion order)
    // Branchless sorted insert ascending; strict '<' keeps earlier index on ties,
    // matching jax.lax.top_k.
    const float ee = __fadd_rn(__fmul_rn(e0, e0), __fmul_rn(e1, e1));
    float t0 = INFINITY, t1 = INFINITY, t2 = INFINITY, t3 = INFINITY, t4 = INFINITY;
    int i0 = 0, i1 = 0, i2 = 0, i3 = 0, i4 = 0;
#pragma unroll 2
    for (int i = 0; i < N_FCNS; ++i) {
        float4 c = sC[i];
        float g = __fadd_rn(__fmul_rn(e0, c.x), __fmul_rn(e1, c.y));
        float d2 = __fadd_rn(__fsub_rn(ee, __fmul_rn(2.0f, g)), c.z);
        bool b0 = d2 < t0, b1 = d2 < t1, b2 = d2 < t2, b3 = d2 < t3, b4 = d2 < t4;
        float m1 = fmaxf(t0, d2);
        float m2 = fmaxf(t1, d2);
        float m3 = fmaxf(t2, d2);
        float m4 = fmaxf(t3, d2);
        int nn1 = b0 ? i0 : i;
        int nn2 = b1 ? i1 : i;
        int nn3 = b2 ? i2 : i;
        int nn4 = b3 ? i3 : i;
        t0 = fminf(t0, d2);
        t1 = fminf(t1, m1);
        t2 = fminf(t2, m2);
        t3 = fminf(t3, m3);
        t4 = fminf(t4, m4);
        i0 = b0 ? i   : i0;
        i1 = b1 ? nn1 : i1;
        i2 = b2 ? nn2 : i2;
        i3 = b3 ? nn3 : i3;
        i4 = b4 ? nn4 : i4;
    }

    // ---------------- accumulate selected PWL functions (nearest-first order) ----
    float sw00 = 0.f, sw01 = 0.f, sw10 = 0.f, sw11 = 0.f, so0 = 0.f, so1 = 0.f;
    int sel[5] = {i0, i1, i2, i3, i4};
#pragma unroll
    for (int k = 0; k < 5; ++k) {
        float4 w = sP4[sel[k]];
        float2 cc = sP2[sel[k]];
        sw00 += w.x; sw01 += w.y; sw10 += w.z; sw11 += w.w;
        so0 += cc.x; so1 += cc.y;
    }
    float o0 = fmaf(sw00, e0, fmaf(sw10, e1, so0));
    float o1 = fmaf(sw01, e0, fmaf(sw11, e1, so1));

    reinterpret_cast<float2*>(out)[s] = make_float2(o0, o1);
}

extern "C" void kernel_launch(void* const* d_in, const int* in_sizes, int n_in,
                              void* d_out, int out_size)
{
    const float* x     = (const float*)d_in[0];
    const float* W0    = (const float*)d_in[1];
    const float* W1    = (const float*)d_in[2];
    const float* W2    = (const float*)d_in[3];
    const float* W3    = (const float*)d_in[4];
    const float* W4    = (const float*)d_in[5];
    const float* Wout  = (const float*)d_in[6];
    const float* bout  = (const float*)d_in[7];
    const float* ctrs  = (const float*)d_in[8];
    const float* wts   = (const float*)d_in[9];
    const float* offs  = (const float*)d_in[10];
    float* out = (float*)d_out;

    int n = in_sizes[0] / 32;
    int grid = (n + BLOCK - 1) / BLOCK;
    densenet_pwlnn_kernel<<<grid, BLOCK>>>(x, W0, W1, W2, W3, W4, Wout, bout,
                                           ctrs, wts, offs, out, n);
}

// round 10
// speedup vs baseline: 4.5408x; 4.5408x over previous
#include <cuda_runtime.h>
#include <math.h>

// DenseNetPWLNN fused kernel.
// Inputs (metadata order): x(524288x32), W0(5x32), W1(5x37), W2(5x42), W3(5x47),
// W4(5x52), Wout(2x57), bout(2), ctrs(250x2), wts(250x2x2), offsets(250x2).
// Output: (524288 x 2) float32.

#define BLOCK 256
#define N_FCNS 250

// padded dense-weight layout in shared memory (rows padded to mult of 4 floats):
// L0: fan 32 pad 32 off    0; L1: fan 37 pad 40 off 160; L2: fan 42 pad 44 off 360
// L3: fan 47 pad 48 off  580; L4: fan 52 pad 52 off 820; Wout: 2x60 off 1080
#define SW_TOT 1200

// ---------------- double-float primitives (explicit intrinsics; never contracted) --
__device__ __forceinline__ float2 two_sum(float a, float b) {
    float s  = __fadd_rn(a, b);
    float bb = __fsub_rn(s, a);
    float e  = __fadd_rn(__fsub_rn(a, __fsub_rn(s, bb)), __fsub_rn(b, bb));
    return make_float2(s, e);
}
__device__ __forceinline__ float2 fast_two_sum(float a, float b) {  // |a| >= |b|
    float s = __fadd_rn(a, b);
    float e = __fadd_rn(__fsub_rn(a, s), b);
    return make_float2(s, e);
}
__device__ __forceinline__ float2 two_prod(float a, float b) {
    float p = __fmul_rn(a, b);
    float e = __fmaf_rn(a, b, -p);
    return make_float2(p, e);
}

// Branch-free double-float tanh, abs error ~2^-38: matches correctly-rounded
// float tanh except ~2^-13 of calls (1-ulp) — measured flip sensitivity makes
// that ~0.02 expected kNN flips over the whole problem.
__device__ __forceinline__ float tanh_df(float x) {
    const float C_HI   = 2.8853900432586669921875f;   // hi(2*log2(e))
    const float C_LO   = 3.85192598e-08f;             // lo
    const float LN2_HI = 0.693147182464599609375f;
    const float LN2_LO = -1.90465430e-09f;
    const float I6_HI  = 0.166666671633720397949f;    // hi(1/6)
    const float I6_LO  = -4.96705394e-09f;
    const float I24_HI = 0.0416666679084300994873f;   // hi(1/24)
    const float I24_LO = -1.24176341e-09f;

    float a = fminf(fabsf(x), 9.6f);   // tanh rounds to 1.0f beyond ~9.011
    // z = a * (2 log2 e)  (df)
    float2 z = two_prod(a, C_HI);
    z.y = __fmaf_rn(a, C_LO, z.y);
    float k  = rintf(z.x);                        // 0..28
    float fh = __fsub_rn(z.x, k);                 // exact
    float2 f = two_sum(fh, z.y);
    // w = f * ln2  (df)
    float2 w;
    {
        float2 p = two_prod(f.x, LN2_HI);
        p.y = __fmaf_rn(f.x, LN2_LO, __fmaf_rn(f.y, LN2_HI, p.y));
        w = fast_two_sum(p.x, p.y);
    }
    // u = w^2 (df)
    float2 u;
    {
        float2 p = two_prod(w.x, w.x);
        p.y = __fmaf_rn(__fadd_rn(w.x, w.x), w.y, p.y);
        u = fast_two_sum(p.x, p.y);
    }
    // w3 = w*u (df)
    float2 w3;
    {
        float2 p = two_prod(w.x, u.x);
        p.y = __fmaf_rn(w.x, u.y, __fmaf_rn(w.y, u.x, p.y));
        w3 = fast_two_sum(p.x, p.y);
    }
    // tail n=5..11 in float
    float w4h = __fmul_rn(u.x, u.x);
    float w5  = __fmul_rn(w4h, w.x);
    float q = 2.50521084e-08f;                    // 1/11!
    q = __fmaf_rn(w.x, q, 2.75573192e-07f);       // 1/10!
    q = __fmaf_rn(w.x, q, 2.75573192e-06f);       // 1/9!
    q = __fmaf_rn(w.x, q, 2.48015873e-05f);       // 1/8!
    q = __fmaf_rn(w.x, q, 1.98412698e-04f);       // 1/7!
    q = __fmaf_rn(w.x, q, 1.38888889e-03f);       // 1/6!
    q = __fmaf_rn(w.x, q, 8.33333333e-03f);       // 1/5!
    float T = __fmul_rn(w5, q);
    // w4/24 (df-lite)
    float d4h = __fmul_rn(w4h, I24_HI);
    float d4l = __fmaf_rn(w4h, I24_HI, -d4h);
    d4l = __fmaf_rn(w4h, I24_LO, d4l);
    // w3/6 (df)
    float2 c3;
    {
        float2 p = two_prod(w3.x, I6_HI);
        p.y = __fmaf_rn(w3.x, I6_LO, __fmaf_rn(w3.y, I6_HI, p.y));
        c3 = fast_two_sum(p.x, p.y);
    }
    // R = (1 + w) + u/2 + w3/6 + (w4/24 + T)
    float2 A = fast_two_sum(1.0f, w.x);
    A.y = __fadd_rn(A.y, w.y);
    float huh = __fmul_rn(u.x, 0.5f), hul = __fmul_rn(u.y, 0.5f);
    float2 R = two_sum(A.x, huh);
    R.y = __fadd_rn(R.y, __fadd_rn(A.y, hul));
    float2 R2 = two_sum(R.x, c3.x);
    R2.y = __fadd_rn(R2.y, __fadd_rn(R.y, c3.y));
    float small = __fadd_rn(d4h, __fadd_rn(d4l, T));
    float2 R3 = fast_two_sum(R2.x, __fadd_rn(R2.y, small));
    // E = 2^k * R   (exact scaling, k in [0,28])
    float scale = __int_as_float(((int)k + 127) << 23);
    float Eh = __fmul_rn(R3.x, scale);
    float El = __fmul_rn(R3.y, scale);
    // denom = E + 1 (df)
    float2 d = two_sum(Eh, 1.0f);
    d.y = __fadd_rn(d.y, El);
    float2 dn = fast_two_sum(d.x, d.y);
    // r = 2/denom (df): fast seed + fma residual correction
    float q0  = __fdividef(2.0f, dn.x);
    float rem = __fmaf_rn(-dn.x, q0, 2.0f);
    rem = __fmaf_rn(-dn.y, q0, rem);
    float q1 = __fmul_rn(rem, __fdividef(1.0f, dn.x));
    // res = 1 - q0 - q1   (1 >= q0, Sterbenz-exact leading cancellation)
    float2 s = fast_two_sum(1.0f, -q0);
    float res = __fadd_rn(s.x, __fsub_rn(s.y, q1));
    return copysignf(res, x);
}

template <int FANv, int FANPv, int OFFv>
__device__ __forceinline__ void dense_layer(const float* __restrict__ sW, float h[60]) {
    float acc[5];
#pragma unroll
    for (int j = 0; j < 5; ++j) {
        // gemm accumulation: acc = 0; ascending-k sequential fma.
        float a = 0.f;
#pragma unroll
        for (int i = 0; i < FANPv; i += 4) {
            float4 w = *reinterpret_cast<const float4*>(&sW[OFFv + j * FANPv + i]);
            a = fmaf(w.x, h[i + 0], a);
            a = fmaf(w.y, h[i + 1], a);
            a = fmaf(w.z, h[i + 2], a);
            a = fmaf(w.w, h[i + 3], a);
        }
        acc[j] = a;
    }
#pragma unroll
    for (int j = 0; j < 5; ++j) h[FANv + j] = tanh_df(acc[j]);
}

__global__ void __launch_bounds__(BLOCK, 3)
densenet_pwlnn_kernel(const float* __restrict__ x,
                      const float* __restrict__ gW0, const float* __restrict__ gW1,
                      const float* __restrict__ gW2, const float* __restrict__ gW3,
                      const float* __restrict__ gW4,
                      const float* __restrict__ gWout, const float* __restrict__ gbout,
                      const float* __restrict__ gctrs, const float* __restrict__ gwts,
                      const float* __restrict__ goffs,
                      float* __restrict__ out, int n)
{
    __shared__ float sW[SW_TOT];
    __shared__ float sb[2];
    __shared__ float4 sC[N_FCNS];    // (cx, cy, |c|^2, 0); |c|^2 = add(mul,mul)
    __shared__ float4 sP4[N_FCNS];   // (w00, w01, w10, w11)
    __shared__ float2 sP2[N_FCNS];   // offsets - wts^T * ctrs

    const int tid = threadIdx.x;

    // ---------------- per-block preprocessing ----------------
    {
        const float* gw[5] = {gW0, gW1, gW2, gW3, gW4};
        const int fan[5]  = {32, 37, 42, 47, 52};
        const int fanp[5] = {32, 40, 44, 48, 52};
        const int off[5]  = {0, 160, 360, 580, 820};
#pragma unroll
        for (int l = 0; l < 5; ++l) {
            int nel = 5 * fanp[l];
            for (int e = tid; e < nel; e += BLOCK) {
                int r = e / fanp[l];
                int c = e - r * fanp[l];
                sW[off[l] + e] = (c < fan[l]) ? gw[l][r * fan[l] + c] : 0.f;
            }
        }
        for (int e = tid; e < 120; e += BLOCK) {
            int r = e / 60, c = e - r * 60;
            sW[1080 + e] = (c < 57) ? gWout[r * 57 + c] : 0.f;
        }
        if (tid < 2) sb[tid] = gbout[tid];
        for (int i = tid; i < N_FCNS; i += BLOCK) {
            float cx = gctrs[2 * i], cy = gctrs[2 * i + 1];
            float c2 = __fadd_rn(__fmul_rn(cx, cx), __fmul_rn(cy, cy));
            sC[i] = make_float4(cx, cy, c2, 0.f);
            float w00 = gwts[4 * i + 0], w01 = gwts[4 * i + 1];
            float w10 = gwts[4 * i + 2], w11 = gwts[4 * i + 3];
            sP4[i] = make_float4(w00, w01, w10, w11);
            float c0 = goffs[2 * i + 0] - (w00 * cx + w10 * cy);
            float c1 = goffs[2 * i + 1] - (w01 * cx + w11 * cy);
            sP2[i] = make_float2(c0, c1);
        }
    }
    __syncthreads();

    const int s = blockIdx.x * BLOCK + tid;
    if (s >= n) return;

    // ---------------- load x row, init padded h ----------------
    float h[60];
    {
        const float4* xr = reinterpret_cast<const float4*>(x + (size_t)s * 32);
#pragma unroll
        for (int k = 0; k < 8; ++k) {
            float4 v = xr[k];
            h[4 * k + 0] = v.x; h[4 * k + 1] = v.y;
            h[4 * k + 2] = v.z; h[4 * k + 3] = v.w;
        }
#pragma unroll
        for (int i = 32; i < 60; ++i) h[i] = 0.f;
    }

    // ---------------- dense tanh net ----------------
    dense_layer<32, 32,   0>(sW, h);
    dense_layer<37, 40, 160>(sW, h);
    dense_layer<42, 44, 360>(sW, h);
    dense_layer<47, 48, 580>(sW, h);
    dense_layer<52, 52, 820>(sW, h);

    // ---------------- enc = h @ Wout^T + bout (bias added AFTER dot) ----------
    float e0, e1;
    {
        float a0 = 0.f, a1 = 0.f;
#pragma unroll
        for (int i = 0; i < 60; i += 4) {
            float4 w0 = *reinterpret_cast<const float4*>(&sW[1080 + i]);
            float4 w1 = *reinterpret_cast<const float4*>(&sW[1140 + i]);
            a0 = fmaf(w0.x, h[i + 0], a0); a1 = fmaf(w1.x, h[i + 0], a1);
            a0 = fmaf(w0.y, h[i + 1], a0); a1 = fmaf(w1.y, h[i + 1], a1);
            a0 = fmaf(w0.z, h[i + 2], a0); a1 = fmaf(w1.z, h[i + 2], a1);
            a0 = fmaf(w0.w, h[i + 3], a0); a1 = fmaf(w1.w, h[i + 3], a1);
        }
        e0 = __fadd_rn(a0, sb[0]);
        e1 = __fadd_rn(a1, sb[1]);
    }

    // ---------------- top-5 smallest d2 (FORM B dot — verified vs reference) ----
    const float ee = __fadd_rn(__fmul_rn(e0, e0), __fmul_rn(e1, e1));
    float t0 = INFINITY, t1 = INFINITY, t2 = INFINITY, t3 = INFINITY, t4 = INFINITY;
    int i0 = 0, i1 = 0, i2 = 0, i3 = 0, i4 = 0;
#pragma unroll 5
    for (int i = 0; i < N_FCNS; ++i) {
        float4 c = sC[i];
        float g = __fadd_rn(__fmul_rn(e0, c.x), __fmul_rn(e1, c.y));
        float d2 = __fadd_rn(__fsub_rn(ee, __fmul_rn(2.0f, g)), c.z);
        bool b0 = d2 < t0, b1 = d2 < t1, b2 = d2 < t2, b3 = d2 < t3, b4 = d2 < t4;
        float m1 = fmaxf(t0, d2);
        float m2 = fmaxf(t1, d2);
        float m3 = fmaxf(t2, d2);
        float m4 = fmaxf(t3, d2);
        int nn1 = b0 ? i0 : i;
        int nn2 = b1 ? i1 : i;
        int nn3 = b2 ? i2 : i;
        int nn4 = b3 ? i3 : i;
        t0 = fminf(t0, d2);
        t1 = fminf(t1, m1);
        t2 = fminf(t2, m2);
        t3 = fminf(t3, m3);
        t4 = fminf(t4, m4);
        i0 = b0 ? i   : i0;
        i1 = b1 ? nn1 : i1;
        i2 = b2 ? nn2 : i2;
        i3 = b3 ? nn3 : i3;
        i4 = b4 ? nn4 : i4;
    }

    // ---------------- accumulate selected PWL functions (nearest-first) ----
    float sw00 = 0.f, sw01 = 0.f, sw10 = 0.f, sw11 = 0.f, so0 = 0.f, so1 = 0.f;
    int sel[5] = {i0, i1, i2, i3, i4};
#pragma unroll
    for (int k = 0; k < 5; ++k) {
        float4 w = sP4[sel[k]];
        float2 cc = sP2[sel[k]];
        sw00 += w.x; sw01 += w.y; sw10 += w.z; sw11 += w.w;
        so0 += cc.x; so1 += cc.y;
    }
    float o0 = fmaf(sw00, e0, fmaf(sw10, e1, so0));
    float o1 = fmaf(sw01, e0, fmaf(sw11, e1, so1));

    reinterpret_cast<float2*>(out)[s] = make_float2(o0, o1);
}

extern "C" void kernel_launch(void* const* d_in, const int* in_sizes, int n_in,
                              void* d_out, int out_size)
{
    const float* x     = (const float*)d_in[0];
    const float* W0    = (const float*)d_in[1];
    const float* W1    = (const float*)d_in[2];
    const float* W2    = (const float*)d_in[3];
    const float* W3    = (const float*)d_in[4];
    const float* W4    = (const float*)d_in[5];
    const float* Wout  = (const float*)d_in[6];
    const float* bout  = (const float*)d_in[7];
    const float* ctrs  = (const float*)d_in[8];
    const float* wts   = (const float*)d_in[9];
    const float* offs  = (const float*)d_in[10];
    float* out = (float*)d_out;

    int n = in_sizes[0] / 32;
    int grid = (n + BLOCK - 1) / BLOCK;
    densenet_pwlnn_kernel<<<grid, BLOCK>>>(x, W0, W1, W2, W3, W4, Wout, bout,
                                           ctrs, wts, offs, out, n);
}

// round 11
// speedup vs baseline: 8.7322x; 1.9231x over previous
#include <cuda_runtime.h>
#include <math.h>
#include <stdint.h>

// DenseNetPWLNN fused kernel + kNN candidate-grid pruning.
// Inputs (metadata order): x(524288x32), W0(5x32), W1(5x37), W2(5x42), W3(5x47),
// W4(5x52), Wout(2x57), bout(2), ctrs(250x2), wts(250x2x2), offsets(250x2).
// Output: (524288 x 2) float32.

#define BLOCK 256
#define N_FCNS 250

#define GRID_N 256                 // 256x256 cells over [-8,8)^2
#define CELL_W (16.0f / GRID_N)    // 0.0625
#define CELL_R 0.04419417382f      // half-diagonal = CELL_W*sqrt(2)/2
#define CAP 48                     // max candidates per cell (else full-scan)

__device__ uint8_t g_cnt[GRID_N * GRID_N];
__device__ __align__(16) uint8_t g_list[GRID_N * GRID_N][CAP];

// padded dense-weight layout in shared memory:
// L0: fan 32 pad 32 off 0; L1: 37/40 @160; L2: 42/44 @360; L3: 47/48 @580;
// L4: 52/52 @820; Wout: 2x60 @1080
#define SW_TOT 1200

// ---------------- double-float primitives (never contracted) ----------------
__device__ __forceinline__ float2 two_sum(float a, float b) {
    float s  = __fadd_rn(a, b);
    float bb = __fsub_rn(s, a);
    float e  = __fadd_rn(__fsub_rn(a, __fsub_rn(s, bb)), __fsub_rn(b, bb));
    return make_float2(s, e);
}
__device__ __forceinline__ float2 fast_two_sum(float a, float b) {  // |a| >= |b|
    float s = __fadd_rn(a, b);
    float e = __fadd_rn(__fsub_rn(a, s), b);
    return make_float2(s, e);
}
__device__ __forceinline__ float2 two_prod(float a, float b) {
    float p = __fmul_rn(a, b);
    float e = __fmaf_rn(a, b, -p);
    return make_float2(p, e);
}

// Branch-free double-float tanh, abs err ~2^-38 (proven flip-free in R9).
__device__ __forceinline__ float tanh_df(float x) {
    const float C_HI   = 2.8853900432586669921875f;
    const float C_LO   = 3.85192598e-08f;
    const float LN2_HI = 0.693147182464599609375f;
    const float LN2_LO = -1.90465430e-09f;
    const float I6_HI  = 0.166666671633720397949f;
    const float I6_LO  = -4.96705394e-09f;
    const float I24_HI = 0.0416666679084300994873f;
    const float I24_LO = -1.24176341e-09f;

    float a = fminf(fabsf(x), 9.6f);
    float2 z = two_prod(a, C_HI);
    z.y = __fmaf_rn(a, C_LO, z.y);
    float k  = rintf(z.x);
    float fh = __fsub_rn(z.x, k);
    float2 f = two_sum(fh, z.y);
    float2 w;
    {
        float2 p = two_prod(f.x, LN2_HI);
        p.y = __fmaf_rn(f.x, LN2_LO, __fmaf_rn(f.y, LN2_HI, p.y));
        w = fast_two_sum(p.x, p.y);
    }
    float2 u;
    {
        float2 p = two_prod(w.x, w.x);
        p.y = __fmaf_rn(__fadd_rn(w.x, w.x), w.y, p.y);
        u = fast_two_sum(p.x, p.y);
    }
    float2 w3;
    {
        float2 p = two_prod(w.x, u.x);
        p.y = __fmaf_rn(w.x, u.y, __fmaf_rn(w.y, u.x, p.y));
        w3 = fast_two_sum(p.x, p.y);
    }
    float w4h = __fmul_rn(u.x, u.x);
    float w5  = __fmul_rn(w4h, w.x);
    float q = 2.50521084e-08f;
    q = __fmaf_rn(w.x, q, 2.75573192e-07f);
    q = __fmaf_rn(w.x, q, 2.75573192e-06f);
    q = __fmaf_rn(w.x, q, 2.48015873e-05f);
    q = __fmaf_rn(w.x, q, 1.98412698e-04f);
    q = __fmaf_rn(w.x, q, 1.38888889e-03f);
    q = __fmaf_rn(w.x, q, 8.33333333e-03f);
    float T = __fmul_rn(w5, q);
    float d4h = __fmul_rn(w4h, I24_HI);
    float d4l = __fmaf_rn(w4h, I24_HI, -d4h);
    d4l = __fmaf_rn(w4h, I24_LO, d4l);
    float2 c3;
    {
        float2 p = two_prod(w3.x, I6_HI);
        p.y = __fmaf_rn(w3.x, I6_LO, __fmaf_rn(w3.y, I6_HI, p.y));
        c3 = fast_two_sum(p.x, p.y);
    }
    float2 A = fast_two_sum(1.0f, w.x);
    A.y = __fadd_rn(A.y, w.y);
    float huh = __fmul_rn(u.x, 0.5f), hul = __fmul_rn(u.y, 0.5f);
    float2 R = two_sum(A.x, huh);
    R.y = __fadd_rn(R.y, __fadd_rn(A.y, hul));
    float2 R2 = two_sum(R.x, c3.x);
    R2.y = __fadd_rn(R2.y, __fadd_rn(R.y, c3.y));
    float small = __fadd_rn(d4h, __fadd_rn(d4l, T));
    float2 R3 = fast_two_sum(R2.x, __fadd_rn(R2.y, small));
    float scale = __int_as_float(((int)k + 127) << 23);
    float Eh = __fmul_rn(R3.x, scale);
    float El = __fmul_rn(R3.y, scale);
    float2 d = two_sum(Eh, 1.0f);
    d.y = __fadd_rn(d.y, El);
    float2 dn = fast_two_sum(d.x, d.y);
    float q0  = __fdividef(2.0f, dn.x);
    float rem = __fmaf_rn(-dn.x, q0, 2.0f);
    rem = __fmaf_rn(-dn.y, q0, rem);
    float q1 = __fmul_rn(rem, __fdividef(1.0f, dn.x));
    float2 s = fast_two_sum(1.0f, -q0);
    float res = __fadd_rn(s.x, __fsub_rn(s.y, q1));
    return copysignf(res, x);
}

// ---------------- setup kernel: build candidate grid ----------------
// Per cell: d5 at cell center p (5th-smallest real distance), include every
// center with d(c,p) <= d5(p) + 2r + eps. Coverage: for any q in cell,
// top-5(q) subset of this list (d5 is 1-Lipschitz). eps=0.02 absorbs all fp32
// rounding noise between this bound and the exact rounded-d2 ranking.
__global__ void build_grid_kernel(const float* __restrict__ gctrs) {
    int cell = blockIdx.x * blockDim.x + threadIdx.x;
    if (cell >= GRID_N * GRID_N) return;
    int cx = cell & (GRID_N - 1);
    int cy = cell >> 8;             // GRID_N = 256
    float px = -8.0f + ((float)cx + 0.5f) * CELL_W;
    float py = -8.0f + ((float)cy + 0.5f) * CELL_W;

    float t0 = INFINITY, t1 = INFINITY, t2 = INFINITY, t3 = INFINITY, t4 = INFINITY;
    for (int i = 0; i < N_FCNS; ++i) {
        float dx = gctrs[2 * i] - px;
        float dy = gctrs[2 * i + 1] - py;
        float d2 = dx * dx + dy * dy;
        float m1 = fmaxf(t0, d2), m2 = fmaxf(t1, d2), m3 = fmaxf(t2, d2), m4 = fmaxf(t3, d2);
        t0 = fminf(t0, d2); t1 = fminf(t1, m1); t2 = fminf(t2, m2);
        t3 = fminf(t3, m3); t4 = fminf(t4, m4);
    }
    float rad = sqrtf(t4) + 2.0f * CELL_R + 0.02f;
    float R2 = rad * rad;

    int cnt = 0;
    for (int i = 0; i < N_FCNS; ++i) {
        float dx = gctrs[2 * i] - px;
        float dy = gctrs[2 * i + 1] - py;
        float d2 = dx * dx + dy * dy;
        if (d2 <= R2) {
            if (cnt < CAP) g_list[cell][cnt] = (uint8_t)i;
            ++cnt;
        }
    }
    g_cnt[cell] = (cnt > CAP) ? 255 : (uint8_t)cnt;
}

template <int FANv, int FANPv, int OFFv>
__device__ __forceinline__ void dense_layer(const float* __restrict__ sW, float h[60]) {
    float acc[5];
#pragma unroll
    for (int j = 0; j < 5; ++j) {
        float a = 0.f;
#pragma unroll
        for (int i = 0; i < FANPv; i += 4) {
            float4 w = *reinterpret_cast<const float4*>(&sW[OFFv + j * FANPv + i]);
            a = fmaf(w.x, h[i + 0], a);
            a = fmaf(w.y, h[i + 1], a);
            a = fmaf(w.z, h[i + 2], a);
            a = fmaf(w.w, h[i + 3], a);
        }
        acc[j] = a;
    }
#pragma unroll
    for (int j = 0; j < 5; ++j) h[FANv + j] = tanh_df(acc[j]);
}

// Exact insert step (FORM B dot + rounded-d2 — verified vs reference in R8).
#define CAND(cidx) { \
    float4 C = sC[cidx]; \
    float g_ = __fadd_rn(__fmul_rn(e0, C.x), __fmul_rn(e1, C.y)); \
    float d2 = __fadd_rn(__fsub_rn(ee, __fmul_rn(2.0f, g_)), C.z); \
    bool b0 = d2 < t0, b1 = d2 < t1, b2 = d2 < t2, b3 = d2 < t3, b4 = d2 < t4; \
    float m1 = fmaxf(t0, d2), m2 = fmaxf(t1, d2), m3 = fmaxf(t2, d2), m4 = fmaxf(t3, d2); \
    int n1 = b0 ? i0 : (cidx), n2 = b1 ? i1 : (cidx), n3 = b2 ? i2 : (cidx), n4 = b3 ? i3 : (cidx); \
    t0 = fminf(t0, d2); t1 = fminf(t1, m1); t2 = fminf(t2, m2); \
    t3 = fminf(t3, m3); t4 = fminf(t4, m4); \
    i0 = b0 ? (cidx) : i0; i1 = b1 ? n1 : i1; i2 = b2 ? n2 : i2; \
    i3 = b3 ? n3 : i3; i4 = b4 ? n4 : i4; }

#define WORD4(WV, BASE) if ((BASE) < cnt) { \
    uint32_t wv_ = (WV); \
    { int c_ = wv_ & 255; CAND(c_); } \
    if ((BASE) + 1 < cnt) { int c_ = (wv_ >> 8) & 255; CAND(c_); } \
    if ((BASE) + 2 < cnt) { int c_ = (wv_ >> 16) & 255; CAND(c_); } \
    if ((BASE) + 3 < cnt) { int c_ = wv_ >> 24; CAND(c_); } }

__global__ void __launch_bounds__(BLOCK, 3)
densenet_pwlnn_kernel(const float* __restrict__ x,
                      const float* __restrict__ gW0, const float* __restrict__ gW1,
                      const float* __restrict__ gW2, const float* __restrict__ gW3,
                      const float* __restrict__ gW4,
                      const float* __restrict__ gWout, const float* __restrict__ gbout,
                      const float* __restrict__ gctrs, const float* __restrict__ gwts,
                      const float* __restrict__ goffs,
                      float* __restrict__ out, int n)
{
    __shared__ float sW[SW_TOT];
    __shared__ float sb[2];
    __shared__ float4 sC[N_FCNS];    // (cx, cy, |c|^2=add(mul,mul), 0)
    __shared__ float4 sP4[N_FCNS];   // (w00, w01, w10, w11)
    __shared__ float2 sP2[N_FCNS];   // offsets - wts^T * ctrs

    const int tid = threadIdx.x;

    // ---------------- per-block preprocessing ----------------
    {
        const float* gw[5] = {gW0, gW1, gW2, gW3, gW4};
        const int fan[5]  = {32, 37, 42, 47, 52};
        const int fanp[5] = {32, 40, 44, 48, 52};
        const int off[5]  = {0, 160, 360, 580, 820};
#pragma unroll
        for (int l = 0; l < 5; ++l) {
            int nel = 5 * fanp[l];
            for (int e = tid; e < nel; e += BLOCK) {
                int r = e / fanp[l];
                int c = e - r * fanp[l];
                sW[off[l] + e] = (c < fan[l]) ? gw[l][r * fan[l] + c] : 0.f;
            }
        }
        for (int e = tid; e < 120; e += BLOCK) {
            int r = e / 60, c = e - r * 60;
            sW[1080 + e] = (c < 57) ? gWout[r * 57 + c] : 0.f;
        }
        if (tid < 2) sb[tid] = gbout[tid];
        for (int i = tid; i < N_FCNS; i += BLOCK) {
            float cx = gctrs[2 * i], cy = gctrs[2 * i + 1];
            float c2 = __fadd_rn(__fmul_rn(cx, cx), __fmul_rn(cy, cy));
            sC[i] = make_float4(cx, cy, c2, 0.f);
            float w00 = gwts[4 * i + 0], w01 = gwts[4 * i + 1];
            float w10 = gwts[4 * i + 2], w11 = gwts[4 * i + 3];
            sP4[i] = make_float4(w00, w01, w10, w11);
            float c0 = goffs[2 * i + 0] - (w00 * cx + w10 * cy);
            float c1 = goffs[2 * i + 1] - (w01 * cx + w11 * cy);
            sP2[i] = make_float2(c0, c1);
        }
    }
    __syncthreads();

    const int s = blockIdx.x * BLOCK + tid;
    if (s >= n) return;

    // ---------------- load x row ----------------
    float h[60];
    {
        const float4* xr = reinterpret_cast<const float4*>(x + (size_t)s * 32);
#pragma unroll
        for (int k = 0; k < 8; ++k) {
            float4 v = xr[k];
            h[4 * k + 0] = v.x; h[4 * k + 1] = v.y;
            h[4 * k + 2] = v.z; h[4 * k + 3] = v.w;
        }
#pragma unroll
        for (int i = 32; i < 60; ++i) h[i] = 0.f;
    }

    // ---------------- dense tanh net ----------------
    dense_layer<32, 32,   0>(sW, h);
    dense_layer<37, 40, 160>(sW, h);
    dense_layer<42, 44, 360>(sW, h);
    dense_layer<47, 48, 580>(sW, h);
    dense_layer<52, 52, 820>(sW, h);

    // ---------------- enc ----------------
    float e0, e1;
    {
        float a0 = 0.f, a1 = 0.f;
#pragma unroll
        for (int i = 0; i < 60; i += 4) {
            float4 w0 = *reinterpret_cast<const float4*>(&sW[1080 + i]);
            float4 w1 = *reinterpret_cast<const float4*>(&sW[1140 + i]);
            a0 = fmaf(w0.x, h[i + 0], a0); a1 = fmaf(w1.x, h[i + 0], a1);
            a0 = fmaf(w0.y, h[i + 1], a0); a1 = fmaf(w1.y, h[i + 1], a1);
            a0 = fmaf(w0.z, h[i + 2], a0); a1 = fmaf(w1.z, h[i + 2], a1);
            a0 = fmaf(w0.w, h[i + 3], a0); a1 = fmaf(w1.w, h[i + 3], a1);
        }
        e0 = __fadd_rn(a0, sb[0]);
        e1 = __fadd_rn(a1, sb[1]);
    }

    // ---------------- top-5 smallest d2 via candidate grid ----------------
    const float ee = __fadd_rn(__fmul_rn(e0, e0), __fmul_rn(e1, e1));
    float t0 = INFINITY, t1 = INFINITY, t2 = INFINITY, t3 = INFINITY, t4 = INFINITY;
    int i0 = 0, i1 = 0, i2 = 0, i3 = 0, i4 = 0;

    int cxi = (int)floorf((e0 + 8.0f) * (1.0f / CELL_W));
    int cyi = (int)floorf((e1 + 8.0f) * (1.0f / CELL_W));
    bool inb = ((unsigned)cxi < GRID_N) && ((unsigned)cyi < GRID_N);
    int cell = inb ? (cyi * GRID_N + cxi) : 0;
    int cnt = inb ? (int)g_cnt[cell] : 255;

    if (cnt != 255) {
        const uint4* lp = reinterpret_cast<const uint4*>(g_list[cell]);
        uint4 LA = lp[0];
        uint4 LB = lp[1];
        uint4 LC = lp[2];
        WORD4(LA.x,  0); WORD4(LA.y,  4); WORD4(LA.z,  8); WORD4(LA.w, 12);
        WORD4(LB.x, 16); WORD4(LB.y, 20); WORD4(LB.z, 24); WORD4(LB.w, 28);
        WORD4(LC.x, 32); WORD4(LC.y, 36); WORD4(LC.z, 40); WORD4(LC.w, 44);
    } else {
        // exact full scan fallback (out-of-grid enc or overflowed cell)
#pragma unroll 2
        for (int i = 0; i < N_FCNS; ++i) {
            CAND(i);
        }
    }

    // ---------------- accumulate selected PWL functions (nearest-first) ----
    float sw00 = 0.f, sw01 = 0.f, sw10 = 0.f, sw11 = 0.f, so0 = 0.f, so1 = 0.f;
    int sel[5] = {i0, i1, i2, i3, i4};
#pragma unroll
    for (int k = 0; k < 5; ++k) {
        float4 w = sP4[sel[k]];
        float2 cc = sP2[sel[k]];
        sw00 += w.x; sw01 += w.y; sw10 += w.z; sw11 += w.w;
        so0 += cc.x; so1 += cc.y;
    }
    float o0 = fmaf(sw00, e0, fmaf(sw10, e1, so0));
    float o1 = fmaf(sw01, e0, fmaf(sw11, e1, so1));

    reinterpret_cast<float2*>(out)[s] = make_float2(o0, o1);
}

extern "C" void kernel_launch(void* const* d_in, const int* in_sizes, int n_in,
                              void* d_out, int out_size)
{
    const float* x     = (const float*)d_in[0];
    const float* W0    = (const float*)d_in[1];
    const float* W1    = (const float*)d_in[2];
    const float* W2    = (const float*)d_in[3];
    const float* W3    = (const float*)d_in[4];
    const float* W4    = (const float*)d_in[5];
    const float* Wout  = (const float*)d_in[6];
    const float* bout  = (const float*)d_in[7];
    const float* ctrs  = (const float*)d_in[8];
    const float* wts   = (const float*)d_in[9];
    const float* offs  = (const float*)d_in[10];
    float* out = (float*)d_out;

    int n = in_sizes[0] / 32;

    build_grid_kernel<<<(GRID_N * GRID_N) / 256, 256>>>(ctrs);

    int grid = (n + BLOCK - 1) / BLOCK;
    densenet_pwlnn_kernel<<<grid, BLOCK>>>(x, W0, W1, W2, W3, W4, Wout, bout,
                                           ctrs, wts, offs, out, n);
}